// round 1
// baseline (speedup 1.0000x reference)
#include <cuda_runtime.h>
#include <math.h>
#include <stdint.h>

#define BB    32
#define NFEAT 80
#define TXD   512
#define TYD   2048
#define NEGV  (-1e9f)
#define LOG2PI_F 1.8378770664093453f

// ---------------- static device scratch (no runtime allocation allowed) ----
__device__ float g_S[(size_t)BB * TYD * TXD];      // 128MB: lp' = mu.y + mm[i], layout [b][j][i]
__device__ float g_mm[BB * TXD];                   // -0.5*sum_c mu^2
__device__ int   g_sout[BB][TXD + 1];              // enter times s_i (e_i = s_{i+1})
__device__ unsigned short g_idx[BB][TYD];          // text index per mel frame
__device__ float g_dur_part[BB];
__device__ float g_prior_part[BB * 8];

// ---------------- K0: mm[b,i] = -0.5 * sum_c mu^2 --------------------------
__global__ void k_mm(const float* __restrict__ mu) {
    int b = blockIdx.x, i = threadIdx.x;            // 512 threads
    const float* p = mu + (size_t)b * NFEAT * TXD + i;
    float s = 0.f;
#pragma unroll
    for (int c = 0; c < NFEAT; c++) { float v = p[(size_t)c * TXD]; s += v * v; }
    g_mm[b * TXD + i] = -0.5f * s;
}

// ---------------- K1: batched GEMM  S[b][j][i] = sum_c y[b,c,j]*mu[b,c,i] + mm[b,i]
// CTA tile: J=64, I=256, 256 threads, 8x8 per thread. Scalar fp32 (precision-safe).
#define GEMM_SMEM (NFEAT * 256 * 4 + NFEAT * 64 * 4)   // 102400 bytes
__global__ __launch_bounds__(256) void k_gemm(const float* __restrict__ mu,
                                              const float* __restrict__ y) {
    extern __shared__ float sm[];
    float* mus = sm;                  // [80][256]
    float* ys  = sm + NFEAT * 256;    // [80][64]
    int b = blockIdx.z;
    int ii0 = blockIdx.x * 256;
    int jj0 = blockIdx.y * 64;
    int tid = threadIdx.x;

    const float* mub = mu + (size_t)b * NFEAT * TXD + ii0;
    for (int idx = tid; idx < NFEAT * 256; idx += 256) {
        int c = idx >> 8, i = idx & 255;
        mus[idx] = mub[(size_t)c * TXD + i];
    }
    const float* yb = y + (size_t)b * NFEAT * TYD + jj0;
    for (int idx = tid; idx < NFEAT * 64; idx += 256) {
        int c = idx >> 6, jj = idx & 63;
        ys[idx] = yb[(size_t)c * TYD + jj];
    }
    __syncthreads();

    int tx = tid & 31, ty = tid >> 5;
    float acc[8][8];
#pragma unroll
    for (int r = 0; r < 8; r++)
#pragma unroll
        for (int k = 0; k < 8; k++) acc[r][k] = 0.f;

#pragma unroll 4
    for (int c = 0; c < NFEAT; c++) {
        const float4 a0 = *(const float4*)(ys + c * 64 + (ty << 3));
        const float4 a1 = *(const float4*)(ys + c * 64 + (ty << 3) + 4);
        const float4 m0 = *(const float4*)(mus + (c << 8) + (tx << 3));
        const float4 m1 = *(const float4*)(mus + (c << 8) + (tx << 3) + 4);
        float av[8] = {a0.x, a0.y, a0.z, a0.w, a1.x, a1.y, a1.z, a1.w};
        float mv[8] = {m0.x, m0.y, m0.z, m0.w, m1.x, m1.y, m1.z, m1.w};
#pragma unroll
        for (int r = 0; r < 8; r++)
#pragma unroll
            for (int k = 0; k < 8; k++) acc[r][k] += av[r] * mv[k];
    }

    const float4 mm0 = *(const float4*)(g_mm + b * TXD + ii0 + (tx << 3));
    const float4 mm1 = *(const float4*)(g_mm + b * TXD + ii0 + (tx << 3) + 4);
    float mmv[8] = {mm0.x, mm0.y, mm0.z, mm0.w, mm1.x, mm1.y, mm1.z, mm1.w};
#pragma unroll
    for (int r = 0; r < 8; r++) {
        int j = jj0 + (ty << 3) + r;
        float* outp = g_S + ((size_t)b * TYD + j) * TXD + ii0 + (tx << 3);
        float4 o0 = make_float4(acc[r][0] + mmv[0], acc[r][1] + mmv[1],
                                acc[r][2] + mmv[2], acc[r][3] + mmv[3]);
        float4 o1 = make_float4(acc[r][4] + mmv[4], acc[r][5] + mmv[5],
                                acc[r][6] + mmv[6], acc[r][7] + mmv[7]);
        *(float4*)outp = o0;
        *(float4*)(outp + 4) = o1;
    }
}

// ---------------- K2: Viterbi DP + in-smem backtrack ------------------------
// 1 CTA/batch, 128 threads, 4 contiguous rows/thread.
// smem: dirs bits [2048][16 u32] (128KB) + cp.async ring (8 cols x 2KB) + bv.
#define DP_DEPTH 8
#define DP_SMEM (TYD * 16 * 4 + DP_DEPTH * TXD * 4 + 2 * 4 * 4)

__global__ __launch_bounds__(128) void k_dp(const int* __restrict__ xl,
                                            const int* __restrict__ yl) {
    extern __shared__ unsigned char smraw[];
    unsigned* dirs = (unsigned*)smraw;                        // [TYD][16]
    float* ring = (float*)(smraw + TYD * 16 * 4);             // [8][512]
    float* bv = ring + DP_DEPTH * TXD;                        // [2][4]

    int b = blockIdx.x;
    int t = threadIdx.x, lane = t & 31, w = t >> 5;
    int xlen = xl[b], ylen = yl[b];
    int r0 = t * 4;
    const float* colbase = g_S + (size_t)b * TYD * TXD + r0;
    unsigned ring_u = (unsigned)__cvta_generic_to_shared(ring);
    unsigned myoff = (unsigned)(r0 * 4);

    // prologue: prefetch cols 0..7
#pragma unroll
    for (int p = 0; p < DP_DEPTH; p++) {
        asm volatile("cp.async.cg.shared.global [%0],[%1],16;\n"
                     :: "r"(ring_u + (unsigned)(p * TXD * 4) + myoff),
                        "l"(colbase + (size_t)p * TXD));
        asm volatile("cp.async.commit_group;\n");
    }
    asm volatile("cp.async.wait_group 7;\n");

    float v[4];
    {
        const float4 lp = *(const float4*)(ring + r0);
        v[0] = (r0 == 0) ? lp.x : NEGV;     // only global row 0 starts live
        v[1] = NEGV; v[2] = NEGV; v[3] = NEGV;
    }
    if (lane == 31) bv[0 * 4 + w] = v[3];
    // issue col 8 into slot 0 (already consumed)
    asm volatile("cp.async.cg.shared.global [%0],[%1],16;\n"
                 :: "r"(ring_u + myoff), "l"(colbase + (size_t)8 * TXD));
    asm volatile("cp.async.commit_group;\n");
    __syncthreads();

    const bool inx0 = (r0 + 0) < xlen, inx1 = (r0 + 1) < xlen;
    const bool inx2 = (r0 + 2) < xlen, inx3 = (r0 + 3) < xlen;

    for (int j = 1; j < ylen; j++) {
        float bvp = NEGV;
        if (lane == 0 && w > 0) bvp = bv[((j - 1) & 1) * 4 + (w - 1)];
        asm volatile("cp.async.wait_group 7;\n");
        int slot = j & 7;
        const float4 lp4 = *(const float4*)(ring + slot * TXD + r0);
        float l0 = inx0 ? lp4.x : NEGV;
        float l1 = inx1 ? lp4.y : NEGV;
        float l2 = inx2 ? lp4.z : NEGV;
        float l3 = inx3 ? lp4.w : NEGV;

        float sh = __shfl_up_sync(0xffffffffu, v[3], 1);
        float vs0 = (lane == 0) ? bvp : sh;
        float vs1 = v[0], vs2 = v[1], vs3 = v[2];

        bool d0 = vs0 >= v[0];
        bool d1 = vs1 >= v[1];
        bool d2 = vs2 >= v[2];
        bool d3 = vs3 >= v[3];
        float n0 = l0 + fmaxf(v[0], vs0);
        float n1 = l1 + fmaxf(v[1], vs1);
        float n2 = l2 + fmaxf(v[2], vs2);
        float n3 = l3 + fmaxf(v[3], vs3);
        v[0] = n0; v[1] = n1; v[2] = n2; v[3] = n3;

        if (lane == 31) bv[(j & 1) * 4 + w] = v[3];

        unsigned m0 = __ballot_sync(0xffffffffu, d0);
        unsigned m1 = __ballot_sync(0xffffffffu, d1);
        unsigned m2 = __ballot_sync(0xffffffffu, d2);
        unsigned m3 = __ballot_sync(0xffffffffu, d3);
        unsigned base = (unsigned)(j * 16 + w * 4);
        if (lane == 0)      dirs[base + 0] = m0;
        else if (lane == 1) dirs[base + 1] = m1;
        else if (lane == 2) dirs[base + 2] = m2;
        else if (lane == 3) dirs[base + 3] = m3;

        int jn = j + DP_DEPTH;
        if (jn < ylen) {
            asm volatile("cp.async.cg.shared.global [%0],[%1],16;\n"
                         :: "r"(ring_u + (unsigned)((jn & 7) * TXD * 4) + myoff),
                            "l"(colbase + (size_t)jn * TXD));
        }
        asm volatile("cp.async.commit_group;\n");
        __syncthreads();
    }

    // default intervals (empty) for rows >= xlen
    for (int i2 = t; i2 <= TXD; i2 += 128) g_sout[b][i2] = ylen;
    __syncthreads();

    // backtrack from smem dirs (serial, lane 0 only)
    if (t == 0) {
        int i = xlen - 1;
        for (int j = ylen - 1; j >= 1; --j) {
            unsigned word = dirs[j * 16 + ((i >> 7) << 2) + (i & 3)];
            if (((word >> ((i >> 2) & 31)) & 1u) && i > 0) {
                g_sout[b][i] = j;   // row i entered at time j
                i--;
            }
        }
        g_sout[b][0] = 0;
    }
}

// ---------------- K3: write attn rows (interval -> ones) + idx map ----------
__global__ void k_attn(float* __restrict__ out, const int* __restrict__ xl,
                       const int* __restrict__ yl) {
    int i = blockIdx.x, b = blockIdx.y, tid = threadIdx.x;   // 256 threads
    int s = g_sout[b][i];
    int e = g_sout[b][i + 1];
    float* row = out + 2 + ((size_t)(b * TXD + i)) * TYD;    // 8B aligned
    for (int p = tid; p < TYD / 2; p += 256) {
        int t0 = p * 2;
        float2 vv;
        vv.x = (t0 >= s && t0 < e) ? 1.f : 0.f;
        vv.y = (t0 + 1 >= s && t0 + 1 < e) ? 1.f : 0.f;
        *(float2*)(row + t0) = vv;
    }
    if (i < xl[b]) {
        for (int tt = s + tid; tt < e; tt += 256)
            g_idx[b][tt] = (unsigned short)i;
    }
}

// ---------------- K4: duration loss partials --------------------------------
__global__ void k_dur(const float* __restrict__ logw, const int* __restrict__ xl) {
    int b = blockIdx.x, i = threadIdx.x;   // 512 threads
    float val = 0.f;
    int xlen = xl[b];
    if (i < xlen) {
        int d = g_sout[b][i + 1] - g_sout[b][i];
        float lw = logw[b * TXD + i];
        float diff = lw - logf(1e-8f + (float)d);
        val = diff * diff;
    }
    __shared__ float red[512];
    red[i] = val;
    __syncthreads();
    for (int off = 256; off > 0; off >>= 1) {
        if (i < off) red[i] += red[i + off];
        __syncthreads();
    }
    if (i == 0) g_dur_part[b] = red[0];
}

// ---------------- K5: prior loss partials -----------------------------------
__global__ void k_prior(const float* __restrict__ mu, const float* __restrict__ y,
                        const int* __restrict__ yl) {
    int b = blockIdx.y;
    int t = blockIdx.x * 256 + threadIdx.x;
    float acc = 0.f;
    if (t < yl[b]) {
        int k = g_idx[b][t];
        const float* yp = y + (size_t)b * NFEAT * TYD + t;
        const float* mp = mu + (size_t)b * NFEAT * TXD + k;
#pragma unroll 8
        for (int c = 0; c < NFEAT; c++) {
            float d = yp[(size_t)c * TYD] - mp[(size_t)c * TXD];
            acc += d * d;
        }
    }
    __shared__ float red[256];
    red[threadIdx.x] = acc;
    __syncthreads();
    for (int off = 128; off > 0; off >>= 1) {
        if (threadIdx.x < off) red[threadIdx.x] += red[threadIdx.x + off];
        __syncthreads();
    }
    if (threadIdx.x == 0) g_prior_part[b * 8 + blockIdx.x] = red[0];
}

// ---------------- K6: finalize scalars (deterministic sums) -----------------
__global__ void k_final(float* __restrict__ out, const int* __restrict__ xl,
                        const int* __restrict__ yl) {
    if (threadIdx.x != 0) return;
    float ds = 0.f;
    for (int b = 0; b < BB; b++) ds += g_dur_part[b];
    float ps = 0.f;
    for (int q = 0; q < BB * 8; q++) ps += g_prior_part[q];
    int sx = 0, sy = 0;
    for (int b = 0; b < BB; b++) { sx += xl[b]; sy += yl[b]; }
    out[0] = ds / (float)sx;
    out[1] = 0.5f * ps / ((float)sy * (float)NFEAT) + 0.5f * LOG2PI_F;
}

// ---------------- launch ----------------------------------------------------
extern "C" void kernel_launch(void* const* d_in, const int* in_sizes, int n_in,
                              void* d_out, int out_size) {
    const float* mu   = (const float*)d_in[0];   // [32,80,512]
    const float* logw = (const float*)d_in[1];   // [32,1,512]
    const float* y    = (const float*)d_in[2];   // [32,80,2048]
    const int*   xl   = (const int*)d_in[3];
    const int*   yl   = (const int*)d_in[4];
    float* out = (float*)d_out;

    cudaFuncSetAttribute(k_gemm, cudaFuncAttributeMaxDynamicSharedMemorySize, GEMM_SMEM);
    cudaFuncSetAttribute(k_dp,   cudaFuncAttributeMaxDynamicSharedMemorySize, DP_SMEM);

    k_mm<<<BB, TXD>>>(mu);
    k_gemm<<<dim3(TXD / 256, TYD / 64, BB), 256, GEMM_SMEM>>>(mu, y);
    k_dp<<<BB, 128, DP_SMEM>>>(xl, yl);
    k_attn<<<dim3(TXD, BB), 256>>>(out, xl, yl);
    k_dur<<<BB, TXD>>>(logw, xl);
    k_prior<<<dim3(TYD / 256, BB), 256>>>(mu, y, yl);
    k_final<<<1, 32>>>(out, xl, yl);
}

// round 4
// speedup vs baseline: 1.4013x; 1.4013x over previous
#include <cuda_runtime.h>
#include <math.h>
#include <stdint.h>

#define BB    32
#define NFEAT 80
#define TXD   512
#define TYD   2048
#define NEGV  (-1e9f)
#define LOG2PI_F 1.8378770664093453f

// ---------------- static device scratch ------------------------------------
__device__ float g_S[(size_t)BB * TYD * TXD];      // lp' = mu.y + mm[i], [b][j][i]
__device__ float g_mm[BB * TXD];
__device__ int   g_sout[BB][TXD + 1];              // enter times s_i (e_i = s_{i+1})
__device__ unsigned short g_idx[BB][TYD];
__device__ float g_dur_part[BB];
__device__ float g_prior_part[BB * 8];

// ---------------- f32x2 packed-FMA helpers ---------------------------------
__device__ __forceinline__ unsigned long long pk2(float x, float y) {
    unsigned long long r; asm("mov.b64 %0, {%1, %2};" : "=l"(r) : "f"(x), "f"(y)); return r;
}
__device__ __forceinline__ unsigned long long fma2(unsigned long long a, unsigned long long b,
                                                   unsigned long long c) {
    unsigned long long d; asm("fma.rn.f32x2 %0, %1, %2, %3;" : "=l"(d) : "l"(a), "l"(b), "l"(c));
    return d;
}
__device__ __forceinline__ unsigned long long add2(unsigned long long a, unsigned long long b) {
    unsigned long long d; asm("add.rn.f32x2 %0, %1, %2;" : "=l"(d) : "l"(a), "l"(b));
    return d;
}

// ---------------- K0: mm[b,i] = -0.5 * sum_c mu^2 --------------------------
__global__ void k_mm(const float* __restrict__ mu) {
    int b = blockIdx.x, i = threadIdx.x;
    const float* p = mu + (size_t)b * NFEAT * TXD + i;
    float s = 0.f;
#pragma unroll
    for (int c = 0; c < NFEAT; c++) { float v = p[(size_t)c * TXD]; s += v * v; }
    g_mm[b * TXD + i] = -0.5f * s;
}

// ---------------- K1: batched GEMM via packed f32x2 FMA ---------------------
#define GEMM_SMEM (NFEAT * 256 * 4 + NFEAT * 64 * 4)   // 102400 bytes
__global__ __launch_bounds__(256) void k_gemm(const float* __restrict__ mu,
                                              const float* __restrict__ y,
                                              const int* __restrict__ yl) {
    int b = blockIdx.z;
    int jj0 = blockIdx.y * 64;
    if (jj0 >= yl[b]) return;                       // columns beyond ylen never read

    extern __shared__ float sm[];
    float* mus = sm;                  // [80][256]
    float* ys  = sm + NFEAT * 256;    // [80][64]
    int ii0 = blockIdx.x * 256;
    int tid = threadIdx.x;

    const float* mub = mu + (size_t)b * NFEAT * TXD + ii0;
    for (int idx = tid; idx < NFEAT * 256; idx += 256) {
        int c = idx >> 8, i = idx & 255;
        mus[idx] = mub[(size_t)c * TXD + i];
    }
    const float* yb = y + (size_t)b * NFEAT * TYD + jj0;
    for (int idx = tid; idx < NFEAT * 64; idx += 256) {
        int c = idx >> 6, jj = idx & 63;
        ys[idx] = yb[(size_t)c * TYD + jj];
    }
    __syncthreads();

    int tx = tid & 31, ty = tid >> 5;
    unsigned long long acc[8][4];
#pragma unroll
    for (int r = 0; r < 8; r++)
#pragma unroll
        for (int k = 0; k < 4; k++) acc[r][k] = 0ULL;

#pragma unroll 4
    for (int c = 0; c < NFEAT; c++) {
        const float4 a0 = *(const float4*)(ys + c * 64 + (ty << 3));
        const float4 a1 = *(const float4*)(ys + c * 64 + (ty << 3) + 4);
        const ulonglong2 m01 = *(const ulonglong2*)(mus + (c << 8) + (tx << 3));
        const ulonglong2 m23 = *(const ulonglong2*)(mus + (c << 8) + (tx << 3) + 4);
        unsigned long long mv[4] = {m01.x, m01.y, m23.x, m23.y};
        float av[8] = {a0.x, a0.y, a0.z, a0.w, a1.x, a1.y, a1.z, a1.w};
#pragma unroll
        for (int r = 0; r < 8; r++) {
            unsigned long long ar = pk2(av[r], av[r]);
#pragma unroll
            for (int k = 0; k < 4; k++) acc[r][k] = fma2(ar, mv[k], acc[r][k]);
        }
    }

    const ulonglong2 mmA = *(const ulonglong2*)(g_mm + b * TXD + ii0 + (tx << 3));
    const ulonglong2 mmB = *(const ulonglong2*)(g_mm + b * TXD + ii0 + (tx << 3) + 4);
    unsigned long long mmv[4] = {mmA.x, mmA.y, mmB.x, mmB.y};
#pragma unroll
    for (int r = 0; r < 8; r++) {
        int j = jj0 + (ty << 3) + r;
        unsigned long long* outp =
            (unsigned long long*)(g_S + ((size_t)b * TYD + j) * TXD + ii0 + (tx << 3));
        ulonglong2 o0, o1;
        o0.x = add2(acc[r][0], mmv[0]); o0.y = add2(acc[r][1], mmv[1]);
        o1.x = add2(acc[r][2], mmv[2]); o1.y = add2(acc[r][3], mmv[3]);
        *(ulonglong2*)outp = o0;
        *(ulonglong2*)(outp + 2) = o1;
    }
}

// ---------------- K2: single-warp Viterbi DP + pipelined backtrack ----------
// 1 warp per batch. Thread t owns rows {128k + 4t .. +3 : k=0..3} in v[k][0..3].
// ring group g=(k*32+t) holds rows 4g..4g+3 -> lane-contiguous LDS/cp.async.
#define DP_DEPTH 8
#define DP_SMEM (TYD * 32 * 2 + DP_DEPTH * TXD * 4)    // 128KB dirs + 16KB ring

__global__ __launch_bounds__(32) void k_dp(const int* __restrict__ xl,
                                           const int* __restrict__ yl) {
    extern __shared__ unsigned char smraw[];
    unsigned short* dirs = (unsigned short*)smraw;            // [TYD][32]
    float* ring = (float*)(smraw + TYD * 32 * 2);             // [8][512]

    int b = blockIdx.x;
    int t = threadIdx.x;
    int xlen = xl[b], ylen = yl[b];
    const float* colbase = g_S + (size_t)b * TYD * TXD;
    unsigned ring_u = (unsigned)__cvta_generic_to_shared(ring);

    // prologue: prefetch columns 0..7
#pragma unroll
    for (int p = 0; p < DP_DEPTH; p++) {
#pragma unroll
        for (int k = 0; k < 4; k++) {
            asm volatile("cp.async.cg.shared.global [%0],[%1],16;\n" ::
                "r"(ring_u + (unsigned)(p * 2048 + (k * 32 + t) * 16)),
                "l"(colbase + (size_t)p * TXD + (k * 32 + t) * 4) : "memory");
        }
        asm volatile("cp.async.commit_group;\n" ::: "memory");
    }
    asm volatile("cp.async.wait_group 7;\n" ::: "memory");

    float v[4][4];
#pragma unroll
    for (int k = 0; k < 4; k++)
#pragma unroll
        for (int m = 0; m < 4; m++) v[k][m] = NEGV;
    if (t == 0) v[0][0] = ring[0];      // lp(0,0): only row 0 alive at j=0

    // refill slot 0 with column 8
#pragma unroll
    for (int k = 0; k < 4; k++) {
        asm volatile("cp.async.cg.shared.global [%0],[%1],16;\n" ::
            "r"(ring_u + (unsigned)((k * 32 + t) * 16)),
            "l"(colbase + (size_t)8 * TXD + (k * 32 + t) * 4) : "memory");
    }
    asm volatile("cp.async.commit_group;\n" ::: "memory");

    const int dyx = ylen - xlen;   // lo(j) = j - dyx

    for (int j = 1; j < ylen; j++) {
        asm volatile("cp.async.wait_group 7;\n" ::: "memory");
        const float* col = ring + (j & 7) * TXD;

        // all shuffles on previous-step values
        float sh[4], tp[3];
        sh[0] = __shfl_up_sync(0xffffffffu, v[0][3], 1);
        sh[1] = __shfl_up_sync(0xffffffffu, v[1][3], 1);
        sh[2] = __shfl_up_sync(0xffffffffu, v[2][3], 1);
        sh[3] = __shfl_up_sync(0xffffffffu, v[3][3], 1);
        tp[0] = __shfl_sync(0xffffffffu, v[0][3], 31);
        tp[1] = __shfl_sync(0xffffffffu, v[1][3], 31);
        tp[2] = __shfl_sync(0xffffffffu, v[2][3], 31);
        if (t == 0) { sh[0] = NEGV; sh[1] = tp[0]; sh[2] = tp[1]; sh[3] = tp[2]; }

        int kmax = j >> 7; if (kmax > 3) kmax = 3;
        int lo = j - dyx;                         // feasibility lower bound
        int kmin = (lo > 0) ? (lo >> 7) : 0;

        unsigned m = 0;
#pragma unroll
        for (int k = 0; k < 4; k++) {
            if (k >= kmin && k <= kmax) {
                float4 l4 = *(const float4*)(col + (k * 32 + t) * 4);
                float vs0 = sh[k], vs1 = v[k][0], vs2 = v[k][1], vs3 = v[k][2];
                float s0 = vs0 - v[k][0];
                float s1 = vs1 - v[k][1];
                float s2 = vs2 - v[k][2];
                float s3 = vs3 - v[k][3];
                v[k][0] = l4.x + fmaxf(v[k][0], vs0);
                v[k][1] = l4.y + fmaxf(v[k][1], vs1);
                v[k][2] = l4.z + fmaxf(v[k][2], vs2);
                v[k][3] = l4.w + fmaxf(v[k][3], vs3);
                // d = (vs >= v) == !sign(vs - v)   (ties -> +0 -> diag, matches >=)
                m |= ((~__float_as_uint(s0)) >> 31) << (k * 4 + 0);
                m |= ((~__float_as_uint(s1)) >> 31) << (k * 4 + 1);
                m |= ((~__float_as_uint(s2)) >> 31) << (k * 4 + 2);
                m |= ((~__float_as_uint(s3)) >> 31) << (k * 4 + 3);
            }
        }
        dirs[j * 32 + t] = (unsigned short)m;

        int jn = j + DP_DEPTH;
        if (jn < ylen) {
#pragma unroll
            for (int k = 0; k < 4; k++) {
                asm volatile("cp.async.cg.shared.global [%0],[%1],16;\n" ::
                    "r"(ring_u + (unsigned)(((jn & 7) * 2048) + (k * 32 + t) * 16)),
                    "l"(colbase + (size_t)jn * TXD + (k * 32 + t) * 4) : "memory");
            }
        }
        asm volatile("cp.async.commit_group;\n" ::: "memory");
    }

    // default (empty) intervals
    for (int i2 = t; i2 <= TXD; i2 += 32) g_sout[b][i2] = ylen;
    __syncwarp();

    // backtrack: pipelined, 4 levels per anchor, speculative candidate loads
    if (t == 0) {
#define TIX(ii) (((ii) >> 2) & 31)
#define DBIT(w, ii) (((w) >> ((((ii) >> 7) << 2) | ((ii) & 3))) & 1)
        int i = xlen - 1;
        int j = ylen - 1;
        while (j >= 4) {
            int q = j * 32;
            unsigned w0  = dirs[q       + TIX(i)];
            unsigned w1a = dirs[q - 32  + TIX(i)],  w1b = dirs[q - 32 + TIX(i - 1)];
            unsigned w2a = dirs[q - 64  + TIX(i)],  w2b = dirs[q - 64 + TIX(i - 1)];
            unsigned w2c = dirs[q - 64  + TIX(i - 2)];
            unsigned w3a = dirs[q - 96  + TIX(i)],  w3b = dirs[q - 96 + TIX(i - 1)];
            unsigned w3c = dirs[q - 96  + TIX(i - 2)], w3d = dirs[q - 96 + TIX(i - 3)];
            int s = 0;
            int d = (i > 0) ? DBIT(w0, i) : 0;
            if (d) { g_sout[b][i] = j; i--; s = 1; }
            unsigned w = s ? w1b : w1a;
            d = (i > 0) ? DBIT(w, i) : 0;
            if (d) { g_sout[b][i] = j - 1; i--; s++; }
            w = (s == 0) ? w2a : (s == 1) ? w2b : w2c;
            d = (i > 0) ? DBIT(w, i) : 0;
            if (d) { g_sout[b][i] = j - 2; i--; s++; }
            w = (s == 0) ? w3a : (s == 1) ? w3b : (s == 2) ? w3c : w3d;
            d = (i > 0) ? DBIT(w, i) : 0;
            if (d) { g_sout[b][i] = j - 3; i--; }
            j -= 4;
        }
        for (; j >= 1; j--) {
            unsigned w = dirs[j * 32 + TIX(i)];
            int d = (i > 0) ? DBIT(w, i) : 0;
            if (d) { g_sout[b][i] = j; i--; }
        }
        g_sout[b][0] = 0;
    }
}

// ---------------- K3: write attn rows + idx map -----------------------------
__global__ void k_attn(float* __restrict__ out, const int* __restrict__ xl,
                       const int* __restrict__ yl) {
    int i = blockIdx.x, b = blockIdx.y, tid = threadIdx.x;   // 256 threads
    int s = g_sout[b][i];
    int e = g_sout[b][i + 1];
    float* row = out + 2 + ((size_t)(b * TXD + i)) * TYD;
    if (tid == 0) {
        row[0] = (0 >= s && 0 < e) ? 1.f : 0.f;
        row[1] = (1 >= s && 1 < e) ? 1.f : 0.f;
    } else if (tid == 1) {
        row[2046] = (2046 >= s && 2046 < e) ? 1.f : 0.f;
        row[2047] = (2047 >= s && 2047 < e) ? 1.f : 0.f;
    }
    for (int g = tid; g < 511; g += 256) {
        int e0 = 2 + 4 * g;
        float4 vv;
        vv.x = (e0 + 0 >= s && e0 + 0 < e) ? 1.f : 0.f;
        vv.y = (e0 + 1 >= s && e0 + 1 < e) ? 1.f : 0.f;
        vv.z = (e0 + 2 >= s && e0 + 2 < e) ? 1.f : 0.f;
        vv.w = (e0 + 3 >= s && e0 + 3 < e) ? 1.f : 0.f;
        *(float4*)(row + e0) = vv;
    }
    if (i < xl[b]) {
        for (int tt = s + tid; tt < e; tt += 256)
            g_idx[b][tt] = (unsigned short)i;
    }
}

// ---------------- K4: duration loss partials --------------------------------
__global__ void k_dur(const float* __restrict__ logw, const int* __restrict__ xl) {
    int b = blockIdx.x, i = threadIdx.x;
    float val = 0.f;
    int xlen = xl[b];
    if (i < xlen) {
        int d = g_sout[b][i + 1] - g_sout[b][i];
        float lw = logw[b * TXD + i];
        float diff = lw - logf(1e-8f + (float)d);
        val = diff * diff;
    }
    __shared__ float red[512];
    red[i] = val;
    __syncthreads();
    for (int off = 256; off > 0; off >>= 1) {
        if (i < off) red[i] += red[i + off];
        __syncthreads();
    }
    if (i == 0) g_dur_part[b] = red[0];
}

// ---------------- K5: prior loss partials -----------------------------------
__global__ void k_prior(const float* __restrict__ mu, const float* __restrict__ y,
                        const int* __restrict__ yl) {
    int b = blockIdx.y;
    int t = blockIdx.x * 256 + threadIdx.x;
    float acc = 0.f;
    if (t < yl[b]) {
        int k = g_idx[b][t];
        const float* yp = y + (size_t)b * NFEAT * TYD + t;
        const float* mp = mu + (size_t)b * NFEAT * TXD + k;
#pragma unroll 8
        for (int c = 0; c < NFEAT; c++) {
            float d = yp[(size_t)c * TYD] - mp[(size_t)c * TXD];
            acc += d * d;
        }
    }
    __shared__ float red[256];
    red[threadIdx.x] = acc;
    __syncthreads();
    for (int off = 128; off > 0; off >>= 1) {
        if (threadIdx.x < off) red[threadIdx.x] += red[threadIdx.x + off];
        __syncthreads();
    }
    if (threadIdx.x == 0) g_prior_part[b * 8 + blockIdx.x] = red[0];
}

// ---------------- K6: finalize scalars --------------------------------------
__global__ void k_final(float* __restrict__ out, const int* __restrict__ xl,
                        const int* __restrict__ yl) {
    if (threadIdx.x != 0) return;
    float ds = 0.f;
    for (int b = 0; b < BB; b++) ds += g_dur_part[b];
    float ps = 0.f;
    for (int q = 0; q < BB * 8; q++) ps += g_prior_part[q];
    int sx = 0, sy = 0;
    for (int b = 0; b < BB; b++) { sx += xl[b]; sy += yl[b]; }
    out[0] = ds / (float)sx;
    out[1] = 0.5f * ps / ((float)sy * (float)NFEAT) + 0.5f * LOG2PI_F;
}

// ---------------- launch ----------------------------------------------------
extern "C" void kernel_launch(void* const* d_in, const int* in_sizes, int n_in,
                              void* d_out, int out_size) {
    const float* mu   = (const float*)d_in[0];
    const float* logw = (const float*)d_in[1];
    const float* y    = (const float*)d_in[2];
    const int*   xl   = (const int*)d_in[3];
    const int*   yl   = (const int*)d_in[4];
    float* out = (float*)d_out;

    cudaFuncSetAttribute(k_gemm, cudaFuncAttributeMaxDynamicSharedMemorySize, GEMM_SMEM);
    cudaFuncSetAttribute(k_dp,   cudaFuncAttributeMaxDynamicSharedMemorySize, DP_SMEM);

    k_mm<<<BB, TXD>>>(mu);
    k_gemm<<<dim3(TXD / 256, TYD / 64, BB), 256, GEMM_SMEM>>>(mu, y, yl);
    k_dp<<<BB, 32, DP_SMEM>>>(xl, yl);
    k_attn<<<dim3(TXD, BB), 256>>>(out, xl, yl);
    k_dur<<<BB, TXD>>>(logw, xl);
    k_prior<<<dim3(TYD / 256, BB), 256>>>(mu, y, yl);
    k_final<<<1, 32>>>(out, xl, yl);
}